// round 9
// baseline (speedup 1.0000x reference)
#include <cuda_runtime.h>

#define BATCH 256
#define NROWS 256
#define MCOLS 256
#define DDIM  32
#define TPB   128                 // 4 warps, 2 rows per thread
#define NWARP 4
#define NBLK  128                 // column pairs
#define ITERS 159                 // NBLK + 31
#define WSLOT 32                  // dist ring depth (power of 2, >= 32)
#define LOG2E 1.4426950408889634f
#define BIGF  (1e8f * LOG2E)      // boundary in scaled (D*log2e) domain

__device__ float g_part[BATCH];
__device__ int   g_count;

typedef unsigned long long u64;

#define FMA_F32X2(d, a, b) \
    asm("fma.rn.f32x2 %0, %1, %2, %0;" : "+l"(d) : "l"(a), "l"(b))
#define UNPACK_F32X2(lo, hi, in) \
    asm("mov.b64 {%0, %1}, %2;" : "=f"(lo), "=f"(hi) : "l"(in))

__device__ __forceinline__ float ex2f(float x) {
    float r; asm("ex2.approx.f32 %0, %1;" : "=f"(r) : "f"(x)); return r;
}
__device__ __forceinline__ float lg2f(float x) {
    float r; asm("lg2.approx.f32 %0, %1;" : "=f"(r) : "f"(x)); return r;
}

// softmin in scaled (D*log2e) domain
__device__ __forceinline__ float softmin3s(float a, float b, float c) {
    float mn = fminf(fminf(a, b), c);
    float s  = ex2f(mn - a) + ex2f(mn - b) + ex2f(mn - c);
    return mn - lg2f(s);
}

// dynamic smem layout (bytes):
//   sy   [16][256] u64   :      0 .. 32768    y chunk-transposed (f32x2 pairs)
//   syn  [256] float     :  32768 .. 33792    |y_j|^2
//   drng [4][32][32] f4  :  33792 .. 99328    per-warp per-lane dist ring
//   wrng [3][128][2] u64 :  99328 .. 105472   cross-warp tagged handoff
//   red  [128] float     : 105472 .. 105984
#define SMEM_BYTES 105984

__global__ __launch_bounds__(TPB)
void sdtw_kernel(const float* __restrict__ X, const float* __restrict__ Y,
                 float* __restrict__ out) {
    extern __shared__ unsigned char smraw[];
    u64*    sy   = (u64*)smraw;
    float*  syn  = (float*)(smraw + 32768);
    float4* drng = (float4*)(smraw + 33792);
    u64*    wrng = (u64*)(smraw + 99328);
    float*  red  = (float*)(smraw + 105472);
    __shared__ int islast;

    const int t    = threadIdx.x;
    const int lane = t & 31;
    const int w    = t >> 5;
    const int b    = blockIdx.x;
    const float* xb = X + (size_t)b * NROWS * DDIM;
    const float* yb = Y + (size_t)b * MCOLS * DDIM;

    // ---- stage y chunk-transposed: sy[c][j] = f32x2(y[j][2c], y[j][2c+1]) ----
    const ulonglong2* yb16 = (const ulonglong2*)yb;
    for (int k = t; k < MCOLS * 8; k += TPB) {
        int j = k >> 3, c2 = k & 7;
        ulonglong2 v = yb16[k];
        sy[(2 * c2)     * 256 + j] = v.x;
        sy[(2 * c2 + 1) * 256 + j] = v.y;
    }
    // ---- y squared norms ----
    for (int j = t; j < MCOLS; j += TPB) {
        const float4* row = (const float4*)(yb + j * DDIM);
        float acc = 0.f;
        #pragma unroll
        for (int c = 0; c < 8; c++) {
            float4 v = row[c];
            acc += v.x * v.x + v.y * v.y + v.z * v.z + v.w * v.w;
        }
        syn[j] = acc;
    }
    // ---- cross-warp ring: tag 0 = not ready ----
    for (int k = t; k < 3 * NBLK * 2; k += TPB) wrng[k] = 0ull;

    // ---- x rows (64w+2lane, +1) as u64 f32x2 chunks (memory-natural packing) ----
    u64 ax0[16], ax1[16];
    float xx0 = 0.f, xx1 = 0.f;
    {
        const ulonglong2* r0 = (const ulonglong2*)(xb + (size_t)(64 * w + 2 * lane)     * DDIM);
        const ulonglong2* r1 = (const ulonglong2*)(xb + (size_t)(64 * w + 2 * lane + 1) * DDIM);
        #pragma unroll
        for (int c2 = 0; c2 < 8; c2++) {
            ulonglong2 v0 = r0[c2], v1 = r1[c2];
            ax0[2*c2] = v0.x; ax0[2*c2+1] = v0.y;
            ax1[2*c2] = v1.x; ax1[2*c2+1] = v1.y;
            float a, bb;
            UNPACK_F32X2(a, bb, v0.x); xx0 += a*a + bb*bb;
            UNPACK_F32X2(a, bb, v0.y); xx0 += a*a + bb*bb;
            UNPACK_F32X2(a, bb, v1.x); xx1 += a*a + bb*bb;
            UNPACK_F32X2(a, bb, v1.y); xx1 += a*a + bb*bb;
        }
    }
    __syncthreads();

    // ---- DP state (scaled domain) ----
    float left0 = BIGF, left1 = BIGF;
    float tl   = (t == 0) ? 0.f : BIGF;
    float pv10 = BIGF, pv11 = BIGF;      // prev iteration bottom-row values (c0, c1)

    volatile u64* wv = wrng;

    #pragma unroll 2
    for (int ib = 0; ib < ITERS; ib++) {
        // neighbor's bottom-row pair from previous iteration (warp-uniform)
        float s10 = __shfl_up_sync(0xffffffffu, pv10, 1);
        float s11 = __shfl_up_sync(0xffffffffu, pv11, 1);

        // ---- produce dist for column pair (2*ib, 2*ib+1), own rows ----
        if (ib < NBLK) {                               // uniform guard
            const int c0 = 2 * ib;
            u64 a00 = 0ull, a10 = 0ull, a01 = 0ull, a11 = 0ull;
            #pragma unroll
            for (int c = 0; c < 16; c++) {
                ulonglong2 y = *(const ulonglong2*)(sy + c * 256 + c0);  // broadcast
                FMA_F32X2(a00, ax0[c], y.x);
                FMA_F32X2(a10, ax1[c], y.x);
                FMA_F32X2(a01, ax0[c], y.y);
                FMA_F32X2(a11, ax1[c], y.y);
            }
            float lo, hi;
            UNPACK_F32X2(lo, hi, a00); float dot00 = lo + hi;
            UNPACK_F32X2(lo, hi, a10); float dot10 = lo + hi;
            UNPACK_F32X2(lo, hi, a01); float dot01 = lo + hi;
            UNPACK_F32X2(lo, hi, a11); float dot11 = lo + hi;
            float yn0 = syn[c0], yn1 = syn[c0 + 1];
            float4 o;
            o.x = fmaxf(fmaf(-2.f, dot00, xx0 + yn0), 0.f) * LOG2E;
            o.y = fmaxf(fmaf(-2.f, dot10, xx1 + yn0), 0.f) * LOG2E;
            o.z = fmaxf(fmaf(-2.f, dot01, xx0 + yn1), 0.f) * LOG2E;
            o.w = fmaxf(fmaf(-2.f, dot11, xx1 + yn1), 0.f) * LOG2E;
            drng[(w * WSLOT + (ib & (WSLOT - 1))) * 32 + lane] = o;
        }

        // ---- consume own dist entry for block bk = ib - lane ----
        const int bk = ib - lane;
        float4 dq = drng[(w * WSLOT + (bk & (WSLOT - 1))) * 32 + lane];

        // ---- up values (boundary row of this thread's 2-row strip) ----
        float up0, up1;
        if (lane == 0) {
            if (w == 0) { up0 = BIGF; up1 = BIGF; }
            else {
                const int rbk = (ib < NBLK) ? ib : (NBLK - 1);
                const unsigned tag = (unsigned)(rbk + 1);
                volatile u64* p = wv + ((w - 1) * NBLK + rbk) * 2;
                u64 w0 = p[0], w1 = p[1];
                while ((unsigned)(w0 >> 32) != tag || (unsigned)(w1 >> 32) != tag) {
                    w0 = p[0]; w1 = p[1];
                }
                up0 = __uint_as_float((unsigned)w0);
                up1 = __uint_as_float((unsigned)w1);
            }
        } else { up0 = s10; up1 = s11; }

        // ---- 2x2 cell tile, chain depth 3 ----
        float v00 = dq.x + softmin3s(up0, left0, tl);
        float v10 = dq.y + softmin3s(v00, left1, left0);
        float v01 = dq.z + softmin3s(up1, v00,   up0);
        float v11 = dq.w + softmin3s(v01, v10,   v00);

        // ---- predicated commit ----
        const bool act = (bk >= 0) && (bk < NBLK);
        tl    = act ? up1 : tl;
        left0 = act ? v01 : left0;
        left1 = act ? v11 : left1;
        pv10  = act ? v10 : pv10;
        pv11  = act ? v11 : pv11;

        if (act && lane == 31 && w < NWARP - 1) {
            u64 tagw = (u64)(unsigned)(bk + 1) << 32;
            wv[(w * NBLK + bk) * 2 + 0] = tagw | (u64)__float_as_uint(v10);
            wv[(w * NBLK + bk) * 2 + 1] = tagw | (u64)__float_as_uint(v11);
        }
        if (w == NWARP - 1 && lane == 31 && bk == NBLK - 1)
            g_part[b] = v11;                 // scaled D[N][M]
    }

    // ---- fused grid reduction (last CTA) ----
    __threadfence();
    __syncthreads();
    if (t == 0) islast = (atomicAdd(&g_count, 1) == BATCH - 1);
    __syncthreads();
    if (islast) {
        __threadfence();
        red[t] = g_part[t] + g_part[t + TPB];
        __syncthreads();
        #pragma unroll
        for (int off = TPB / 2; off > 0; off >>= 1) {
            if (t < off) red[t] += red[t + off];
            __syncthreads();
        }
        if (t == 0) {
            out[0] = red[0] * (1.0f / ((float)BATCH * LOG2E));
            g_count = 0;                     // reset for next graph replay
        }
    }
}

extern "C" void kernel_launch(void* const* d_in, const int* in_sizes, int n_in,
                              void* d_out, int out_size) {
    const float* x = (const float*)d_in[0];
    const float* y = (const float*)d_in[1];
    float* out = (float*)d_out;
    cudaFuncSetAttribute(sdtw_kernel, cudaFuncAttributeMaxDynamicSharedMemorySize,
                         SMEM_BYTES);
    sdtw_kernel<<<BATCH, TPB, SMEM_BYTES>>>(x, y, out);
}

// round 10
// speedup vs baseline: 1.9986x; 1.9986x over previous
#include <cuda_runtime.h>

#define BATCH 256
#define NROWS 256
#define MCOLS 256
#define DDIM  32
#define TPB   256                 // warps 0-3: dist producers, 4-7: DP consumers
#define RING  64                  // dist ring depth (columns), power of 2
#define CITER 287                 // MCOLS + 31 consumer iterations
#define LOG2E 1.4426950408889634f
#define BIGF  (1e8f * LOG2E)      // boundary in scaled (D*log2e) domain

__device__ float g_part[BATCH];
__device__ int   g_count;

typedef unsigned long long u64;

#define FMA_F32X2(d, a, b) \
    asm("fma.rn.f32x2 %0, %1, %2, %0;" : "+l"(d) : "l"(a), "l"(b))
#define UNPACK_F32X2(lo, hi, in) \
    asm("mov.b64 {%0, %1}, %2;" : "=f"(lo), "=f"(hi) : "l"(in))

__device__ __forceinline__ float ex2f(float x) {
    float r; asm("ex2.approx.f32 %0, %1;" : "=f"(r) : "f"(x)); return r;
}
__device__ __forceinline__ float lg2f(float x) {
    float r; asm("lg2.approx.f32 %0, %1;" : "=f"(r) : "f"(x)); return r;
}
__device__ __forceinline__ float softmin3s(float a, float b, float c) {
    float mn = fminf(fminf(a, b), c);
    float s  = ex2f(mn - a) + ex2f(mn - b) + ex2f(mn - c);
    return mn - lg2f(s);
}

// dynamic smem layout (bytes)
#define OFF_SY    0        // ulonglong2[8][256]      y chunk-transposed   32768
#define OFF_SYN   32768    // float[256]   |y_j|^2                          1024
#define OFF_RING  33792    // float2[4][RING][32]  dist ring               65536
#define OFF_TAGP  99328    // int[4][256]  column-ready tags                4096
#define OFF_WRNG  103424   // u64[3][256]  dp cross-warp tagged handoff     6144
#define OFF_CONS  109568   // int[4] consumed counters (+pad)                 64
#define OFF_RED   109632   // float[256] reduction                          1024
#define SMEM_BYTES 110656

__global__ void __launch_bounds__(TPB, 2)
sdtw_kernel(const float* __restrict__ X, const float* __restrict__ Y,
            float* __restrict__ out) {
    extern __shared__ unsigned char sm[];
    ulonglong2*    sy16 = (ulonglong2*)(sm + OFF_SY);
    float*         syn  = (float*)(sm + OFF_SYN);
    float2*        ring = (float2*)(sm + OFF_RING);
    volatile int*  tagp = (volatile int*)(sm + OFF_TAGP);
    u64*           wrng = (u64*)(sm + OFF_WRNG);
    volatile int*  cons = (volatile int*)(sm + OFF_CONS);
    float*         red  = (float*)(sm + OFF_RED);
    __shared__ int islast;

    const int t    = threadIdx.x;
    const int lane = t & 31;
    const int wid  = t >> 5;
    const int b    = blockIdx.x;
    const float* xb = X + (size_t)b * NROWS * DDIM;
    const float* yb = Y + (size_t)b * MCOLS * DDIM;

    // ---- stage y chunk-transposed: sy16[c2][j] = float4 #c2 of y col j ----
    const ulonglong2* yb16 = (const ulonglong2*)yb;
    for (int k = t; k < MCOLS * 8; k += TPB) {
        int j = k >> 3, c2 = k & 7;
        sy16[c2 * 256 + j] = yb16[k];
    }
    { // |y_j|^2 (t indexes columns exactly once)
        const float4* row = (const float4*)(yb + t * DDIM);
        float acc = 0.f;
        #pragma unroll
        for (int c = 0; c < 8; c++) {
            float4 v = row[c];
            acc += v.x * v.x + v.y * v.y + v.z * v.z + v.w * v.w;
        }
        syn[t] = acc;
    }
    for (int k = t; k < 4 * 256; k += TPB) ((int*)(sm + OFF_TAGP))[k] = 0;
    for (int k = t; k < 3 * 256; k += TPB) wrng[k] = 0ull;
    if (t < 4) ((int*)(sm + OFF_CONS))[t] = -1000000;

    // producers pre-load their x rows (before the sync; consumers skip)
    u64 ax0[16], ax1[16];
    float xx0 = 0.f, xx1 = 0.f;
    if (wid < 4) {
        const ulonglong2* r0 = (const ulonglong2*)(xb + (size_t)(64 * wid + 2 * lane)     * DDIM);
        const ulonglong2* r1 = (const ulonglong2*)(xb + (size_t)(64 * wid + 2 * lane + 1) * DDIM);
        #pragma unroll
        for (int c2 = 0; c2 < 8; c2++) {
            ulonglong2 v0 = r0[c2], v1 = r1[c2];
            ax0[2*c2] = v0.x; ax0[2*c2+1] = v0.y;
            ax1[2*c2] = v1.x; ax1[2*c2+1] = v1.y;
            float a, bb;
            UNPACK_F32X2(a, bb, v0.x); xx0 += a*a + bb*bb;
            UNPACK_F32X2(a, bb, v0.y); xx0 += a*a + bb*bb;
            UNPACK_F32X2(a, bb, v1.x); xx1 += a*a + bb*bb;
            UNPACK_F32X2(a, bb, v1.y); xx1 += a*a + bb*bb;
        }
    }
    __syncthreads();

    if (wid < 4) {
        // ================= PRODUCER warp p: rows 64p+2l, 64p+2l+1 =================
        const int p = wid;
        unsigned rb;
        {   // smem byte address of ring[p][0][lane]
            void* gp = (void*)(ring + (p * RING) * 32 + lane);
            rb = (unsigned)__cvta_generic_to_shared(gp);
        }
        volatile int* myc = cons + p;
        #pragma unroll 1
        for (int j = 0; j < MCOLS; j++) {
            if (j >= RING) {                       // backpressure (uniform, slack ~30 cols)
                while (*myc < j - (RING - 1)) __nanosleep(64);
            }
            u64 a00 = 0ull, a01 = 0ull, a10 = 0ull, a11 = 0ull;
            #pragma unroll
            for (int c2 = 0; c2 < 8; c2++) {
                ulonglong2 yv = sy16[c2 * 256 + j];     // broadcast LDS.128
                FMA_F32X2(a00, ax0[2*c2],   yv.x);
                FMA_F32X2(a01, ax0[2*c2+1], yv.y);
                FMA_F32X2(a10, ax1[2*c2],   yv.x);
                FMA_F32X2(a11, ax1[2*c2+1], yv.y);
            }
            float lo, hi, d0, d1;
            UNPACK_F32X2(lo, hi, a00); d0  = lo + hi;
            UNPACK_F32X2(lo, hi, a01); d0 += lo + hi;
            UNPACK_F32X2(lo, hi, a10); d1  = lo + hi;
            UNPACK_F32X2(lo, hi, a11); d1 += lo + hi;
            float yn = syn[j];
            d0 = fmaxf(fmaf(-2.f, d0, xx0 + yn), 0.f) * LOG2E;
            d1 = fmaxf(fmaf(-2.f, d1, xx1 + yn), 0.f) * LOG2E;
            unsigned a = rb + (unsigned)((j & (RING - 1)) * 32 * 8);
            asm volatile("st.volatile.shared.v2.f32 [%0], {%1, %2};"
                         :: "r"(a), "f"(d0), "f"(d1));
            __syncwarp();
            if (lane == 0) tagp[p * 256 + j] = 1;  // column j ready
        }
    } else {
        // ================= CONSUMER warp c: DP rows 64c+2l, +1 (R6 body) =========
        const int c = wid - 4;
        unsigned rb;
        {
            void* gp = (void*)(ring + (c * RING) * 32 + lane);
            rb = (unsigned)__cvta_generic_to_shared(gp);
        }
        volatile int* mytag = tagp + c * 256;
        volatile int* myc   = cons + c;
        volatile u64* myw   = wrng + c * 256;        // valid if c<3
        volatile u64* upw   = wrng + (c - 1) * 256;  // valid if c>0

        float left0 = BIGF, left1 = BIGF;
        float tl = (c == 0 && lane == 0) ? 0.f : BIGF;

        #pragma unroll 1
        for (int i = 0; i < CITER; i++) {
            float s1 = __shfl_up_sync(0xffffffffu, left1, 1);
            const int ii = (i < MCOLS) ? i : (MCOLS - 1);

            while (mytag[ii] == 0) {}               // uniform; in-order production

            const int jj = i - lane;
            unsigned a = rb + (unsigned)((jj & (RING - 1)) * 32 * 8);
            float dx, dy;
            asm volatile("ld.volatile.shared.v2.f32 {%0, %1}, [%2];"
                         : "=f"(dx), "=f"(dy) : "r"(a));

            float up0;
            if (lane == 0) {
                if (c == 0) up0 = BIGF;
                else {
                    u64 wv0 = upw[ii];
                    while ((unsigned)(wv0 >> 32) != (unsigned)(ii + 1)) wv0 = upw[ii];
                    up0 = __uint_as_float((unsigned)wv0);
                }
                if ((i & 7) == 7) *myc = i - 32;    // free ring slots (coarse)
            } else up0 = s1;

            float v0  = dx + softmin3s(up0, left0, tl);
            float nv1 = dy + softmin3s(v0,  left1, left0);

            const bool act = (jj >= 0) && (jj < MCOLS);
            tl    = act ? up0 : tl;
            left0 = act ? v0  : left0;
            left1 = act ? nv1 : left1;

            if (act && lane == 31 && c < 3)
                myw[jj] = ((u64)(unsigned)(jj + 1) << 32) | (u64)__float_as_uint(nv1);
            if (c == 3 && lane == 31 && jj == MCOLS - 1)
                g_part[b] = nv1;                    // scaled D[N][M]
        }
    }

    // ---- fused grid reduction (last CTA) ----
    __threadfence();
    __syncthreads();
    if (t == 0) islast = (atomicAdd(&g_count, 1) == BATCH - 1);
    __syncthreads();
    if (islast) {
        __threadfence();
        red[t] = g_part[t];
        __syncthreads();
        #pragma unroll
        for (int off = TPB / 2; off > 0; off >>= 1) {
            if (t < off) red[t] += red[t + off];
            __syncthreads();
        }
        if (t == 0) {
            out[0] = red[0] * (1.0f / ((float)BATCH * LOG2E));
            g_count = 0;                            // reset for next graph replay
        }
    }
}

extern "C" void kernel_launch(void* const* d_in, const int* in_sizes, int n_in,
                              void* d_out, int out_size) {
    const float* x = (const float*)d_in[0];
    const float* y = (const float*)d_in[1];
    float* out = (float*)d_out;
    cudaFuncSetAttribute(sdtw_kernel, cudaFuncAttributeMaxDynamicSharedMemorySize,
                         SMEM_BYTES);
    sdtw_kernel<<<BATCH, TPB, SMEM_BYTES>>>(x, y, out);
}

// round 11
// speedup vs baseline: 2.2638x; 1.1327x over previous
#include <cuda_runtime.h>

#define BATCH 256
#define NROWS 256
#define MCOLS 256
#define DDIM  32
#define TPB   256                 // warps 0-3: dist producers, 4-7: DP consumers
#define NBLK  128                 // column pairs
#define CITER 159                 // NBLK + 31 consumer iterations
#define RING2 34                  // dist ring depth in blocks (68 columns)
#define LOG2E 1.4426950408889634f
#define BIGF  (1e8f * LOG2E)      // boundary in scaled (D*log2e) domain

__device__ float g_part[BATCH];
__device__ int   g_count;

typedef unsigned long long u64;

#define FMA_F32X2(d, a, b) \
    asm("fma.rn.f32x2 %0, %1, %2, %0;" : "+l"(d) : "l"(a), "l"(b))
#define UNPACK_F32X2(lo, hi, in) \
    asm("mov.b64 {%0, %1}, %2;" : "=f"(lo), "=f"(hi) : "l"(in))

__device__ __forceinline__ float ex2f(float x) {
    float r; asm("ex2.approx.f32 %0, %1;" : "=f"(r) : "f"(x)); return r;
}
__device__ __forceinline__ float lg2f(float x) {
    float r; asm("lg2.approx.f32 %0, %1;" : "=f"(r) : "f"(x)); return r;
}
__device__ __forceinline__ float softmin3s(float a, float b, float c) {
    float mn = fminf(fminf(a, b), c);
    float s  = ex2f(mn - a) + ex2f(mn - b) + ex2f(mn - c);
    return mn - lg2f(s);
}

// dynamic smem layout (bytes)
#define OFF_SY    0        // ulonglong2[8][256]  y chunk-transposed        32768
#define OFF_SYN   32768    // float[256] |y_j|^2  (reused for reduction)     1024
#define OFF_RING  33792    // float4[4][RING2][32] dist ring                69632
#define OFF_PROG  103424   // int[4] producer progress (blocks done) + pad    128
#define OFF_WRNG  103552   // ulonglong2[3][NBLK] dp handoff (2 tagged u64)  6144
#define OFF_CONS  109696   // int[4] consumer progress + pad                  128
#define SMEM_BYTES 109824

__global__ void __launch_bounds__(TPB, 2)
sdtw_kernel(const float* __restrict__ X, const float* __restrict__ Y,
            float* __restrict__ out) {
    extern __shared__ unsigned char sm[];
    ulonglong2*    sy16 = (ulonglong2*)(sm + OFF_SY);
    float*         syn  = (float*)(sm + OFF_SYN);
    volatile int*  prog = (volatile int*)(sm + OFF_PROG);
    volatile int*  cons = (volatile int*)(sm + OFF_CONS);
    __shared__ int islast;

    const int t    = threadIdx.x;
    const int lane = t & 31;
    const int wid  = t >> 5;
    const int b    = blockIdx.x;
    const float* xb = X + (size_t)b * NROWS * DDIM;
    const float* yb = Y + (size_t)b * MCOLS * DDIM;

    // ---- stage y chunk-transposed: sy16[c2][j] = float4 #c2 of y col j ----
    const ulonglong2* yb16 = (const ulonglong2*)yb;
    for (int k = t; k < MCOLS * 8; k += TPB) {
        int j = k >> 3, c2 = k & 7;
        sy16[c2 * 256 + j] = yb16[k];
    }
    {   // |y_j|^2
        const float4* row = (const float4*)(yb + t * DDIM);
        float acc = 0.f;
        #pragma unroll
        for (int c = 0; c < 8; c++) {
            float4 v = row[c];
            acc += v.x * v.x + v.y * v.y + v.z * v.z + v.w * v.w;
        }
        syn[t] = acc;
    }
    for (int k = t; k < 3 * NBLK * 2; k += TPB) ((u64*)(sm + OFF_WRNG))[k] = 0ull;
    if (t < 4) { ((int*)(sm + OFF_PROG))[t] = 0; ((int*)(sm + OFF_CONS))[t] = 0; }

    // producers pre-load their x rows
    u64 ax0[16], ax1[16];
    float xx0 = 0.f, xx1 = 0.f;
    if (wid < 4) {
        const ulonglong2* r0 = (const ulonglong2*)(xb + (size_t)(64 * wid + 2 * lane)     * DDIM);
        const ulonglong2* r1 = (const ulonglong2*)(xb + (size_t)(64 * wid + 2 * lane + 1) * DDIM);
        #pragma unroll
        for (int c2 = 0; c2 < 8; c2++) {
            ulonglong2 v0 = r0[c2], v1 = r1[c2];
            ax0[2*c2] = v0.x; ax0[2*c2+1] = v0.y;
            ax1[2*c2] = v1.x; ax1[2*c2+1] = v1.y;
            float a, bb;
            UNPACK_F32X2(a, bb, v0.x); xx0 += a*a + bb*bb;
            UNPACK_F32X2(a, bb, v0.y); xx0 += a*a + bb*bb;
            UNPACK_F32X2(a, bb, v1.x); xx1 += a*a + bb*bb;
            UNPACK_F32X2(a, bb, v1.y); xx1 += a*a + bb*bb;
        }
    }
    __syncthreads();

    if (wid < 4) {
        // ============ PRODUCER warp p: rows 64p+2l, +1; blocks of 2 cols ============
        const int p = wid;
        unsigned rbase;
        {   void* gp = (void*)(sm + OFF_RING + (size_t)p * RING2 * 32 * 16 + lane * 16);
            rbase = (unsigned)__cvta_generic_to_shared(gp); }
        unsigned paddr;
        {   void* gp = (void*)(prog + p);
            paddr = (unsigned)__cvta_generic_to_shared(gp); }
        volatile int* myc = cons + p;
        int slot = 0;
        #pragma unroll 1
        for (int j = 0; j < NBLK; j++) {
            if (j >= RING2) {                      // backpressure (uniform)
                while (*myc < j - (RING2 - 1)) __nanosleep(32);
            }
            const int c0 = 2 * j;
            u64 a00 = 0ull, a10 = 0ull, a01 = 0ull, a11 = 0ull;
            #pragma unroll
            for (int c2 = 0; c2 < 8; c2++) {
                ulonglong2 y0 = sy16[c2 * 256 + c0];      // broadcast LDS.128
                ulonglong2 y1 = sy16[c2 * 256 + c0 + 1];
                FMA_F32X2(a00, ax0[2*c2],   y0.x);
                FMA_F32X2(a00, ax0[2*c2+1], y0.y);
                FMA_F32X2(a10, ax1[2*c2],   y0.x);
                FMA_F32X2(a10, ax1[2*c2+1], y0.y);
                FMA_F32X2(a01, ax0[2*c2],   y1.x);
                FMA_F32X2(a01, ax0[2*c2+1], y1.y);
                FMA_F32X2(a11, ax1[2*c2],   y1.x);
                FMA_F32X2(a11, ax1[2*c2+1], y1.y);
            }
            float lo, hi, d00, d10, d01, d11;
            UNPACK_F32X2(lo, hi, a00); d00 = lo + hi;
            UNPACK_F32X2(lo, hi, a10); d10 = lo + hi;
            UNPACK_F32X2(lo, hi, a01); d01 = lo + hi;
            UNPACK_F32X2(lo, hi, a11); d11 = lo + hi;
            float yn0 = syn[c0], yn1 = syn[c0 + 1];
            d00 = fmaxf(fmaf(-2.f, d00, xx0 + yn0), 0.f) * LOG2E;
            d10 = fmaxf(fmaf(-2.f, d10, xx1 + yn0), 0.f) * LOG2E;
            d01 = fmaxf(fmaf(-2.f, d01, xx0 + yn1), 0.f) * LOG2E;
            d11 = fmaxf(fmaf(-2.f, d11, xx1 + yn1), 0.f) * LOG2E;
            unsigned a = rbase + (unsigned)(slot * 512);
            asm volatile("st.volatile.shared.v4.f32 [%0], {%1, %2, %3, %4};"
                         :: "r"(a), "f"(d00), "f"(d10), "f"(d01), "f"(d11));
            __syncwarp();
            if (lane == 0)
                asm volatile("st.volatile.shared.s32 [%0], %1;" :: "r"(paddr), "r"(j + 1));
            slot = (slot + 1 == RING2) ? 0 : slot + 1;
        }
    } else {
        // ============ CONSUMER warp c: DP rows 64c+2l, +1; 2x2 tiles ============
        const int c = wid - 4;
        unsigned rbase;
        {   void* gp = (void*)(sm + OFF_RING + (size_t)c * RING2 * 32 * 16 + lane * 16);
            rbase = (unsigned)__cvta_generic_to_shared(gp); }
        volatile int* myprog = prog + c;
        unsigned caddr;
        {   void* gp = (void*)(cons + c);
            caddr = (unsigned)__cvta_generic_to_shared(gp); }
        u64* wrng = (u64*)(sm + OFF_WRNG);
        volatile u64* myw = wrng + (size_t)c * NBLK * 2;        // if c<3
        unsigned upbase = 0;
        if (c > 0) {
            void* gp = (void*)(wrng + (size_t)(c - 1) * NBLK * 2);
            upbase = (unsigned)__cvta_generic_to_shared(gp);
        }

        float left0 = BIGF, left1 = BIGF;
        float tl   = (c == 0 && lane == 0) ? 0.f : BIGF;
        float pv10 = BIGF, pv11 = BIGF;
        int slot = (RING2 - (lane % RING2)) % RING2;            // slot of bk=i-lane

        #pragma unroll 1
        for (int i = 0; i < CITER; i++) {
            float s10 = __shfl_up_sync(0xffffffffu, pv10, 1);
            float s11 = __shfl_up_sync(0xffffffffu, pv11, 1);

            // producer-ready poll (uniform broadcast; first-try hit in steady state)
            {
                const int need = (i + 1 < NBLK) ? i + 1 : NBLK;
                while (*myprog < need) {}
            }

            // own dist tile for block bk = i - lane
            unsigned a = rbase + (unsigned)(slot * 512);
            float dx, dy, dz, dw;
            asm volatile("ld.volatile.shared.v4.f32 {%0, %1, %2, %3}, [%4];"
                         : "=f"(dx), "=f"(dy), "=f"(dz), "=f"(dw) : "r"(a));

            // cross-warp up pair: all lanes read + uniform spin, SEL into lane 0
            float up0 = BIGF, up1 = BIGF;
            if (c > 0) {
                const int ii = (i < NBLK) ? i : (NBLK - 1);
                const unsigned tag = (unsigned)(ii + 1);
                unsigned ua = upbase + (unsigned)(ii * 16);
                u64 w0, w1;
                asm volatile("ld.volatile.shared.v2.u64 {%0, %1}, [%2];"
                             : "=l"(w0), "=l"(w1) : "r"(ua));
                while ((unsigned)(w0 >> 32) != tag || (unsigned)(w1 >> 32) != tag) {
                    asm volatile("ld.volatile.shared.v2.u64 {%0, %1}, [%2];"
                                 : "=l"(w0), "=l"(w1) : "r"(ua));
                }
                up0 = __uint_as_float((unsigned)w0);
                up1 = __uint_as_float((unsigned)w1);
            }
            up0 = (lane == 0) ? up0 : s10;
            up1 = (lane == 0) ? up1 : s11;

            // 2x2 cell tile, chain depth 3
            float v00 = dx + softmin3s(up0, left0, tl);
            float v10 = dy + softmin3s(v00, left1, left0);
            float v01 = dz + softmin3s(up1, v00,   up0);
            float v11 = dw + softmin3s(v01, v10,   v00);

            const int bk = i - lane;
            const bool act = (bk >= 0) && (bk < NBLK);
            tl    = act ? up1 : tl;
            left0 = act ? v01 : left0;
            left1 = act ? v11 : left1;
            pv10  = act ? v10 : pv10;
            pv11  = act ? v11 : pv11;

            if (lane == 31) {   // free ring slots (consumed through bk = i-31)
                asm volatile("st.volatile.shared.s32 [%0], %1;"
                             :: "r"(caddr), "r"(i - 30));
            }
            if (act && lane == 31 && c < 3) {
                u64 tagw = (u64)(unsigned)(bk + 1) << 32;
                myw[bk * 2 + 0] = tagw | (u64)__float_as_uint(v10);
                myw[bk * 2 + 1] = tagw | (u64)__float_as_uint(v11);
            }
            if (c == 3 && lane == 31 && bk == NBLK - 1)
                g_part[b] = v11;                    // scaled D[N][M]

            slot = (slot + 1 == RING2) ? 0 : slot + 1;
        }
    }

    // ---- fused grid reduction (last CTA); reuse syn[] as scratch ----
    __threadfence();
    __syncthreads();
    if (t == 0) islast = (atomicAdd(&g_count, 1) == BATCH - 1);
    __syncthreads();
    if (islast) {
        __threadfence();
        float* red = syn;
        red[t] = g_part[t];
        __syncthreads();
        #pragma unroll
        for (int off = TPB / 2; off > 0; off >>= 1) {
            if (t < off) red[t] += red[t + off];
            __syncthreads();
        }
        if (t == 0) {
            out[0] = red[0] * (1.0f / ((float)BATCH * LOG2E));
            g_count = 0;                            // reset for next graph replay
        }
    }
}

extern "C" void kernel_launch(void* const* d_in, const int* in_sizes, int n_in,
                              void* d_out, int out_size) {
    const float* x = (const float*)d_in[0];
    const float* y = (const float*)d_in[1];
    float* out = (float*)d_out;
    cudaFuncSetAttribute(sdtw_kernel, cudaFuncAttributeMaxDynamicSharedMemorySize,
                         SMEM_BYTES);
    sdtw_kernel<<<BATCH, TPB, SMEM_BYTES>>>(x, y, out);
}